// round 5
// baseline (speedup 1.0000x reference)
#include <cuda_runtime.h>
#include <math.h>

// Problem dims
#define BB 256
#define SS 512
#define FF 26
#define HH 512
#define MM 256
#define CC 20

// LSTM kernel config
#define NBLK 128        // hidden-unit tiles (4 units each)
#define JT 4            // hidden units per block
#define NROW 16         // 4 gates * JT rows
#define NTHR 128        // one thread per batch-pair

#define LSTM_SMEM ((NROW*HH*2 + NROW*28*2 + NROW) * 4)
#define MLP1_SMEM ((16*HH*2 + 16) * 4)

// ---------------- scratch (static __device__, allocation-free) ----------------
__device__ float g_xT[SS * FF * BB];          // x transposed: [t][f][b]
__device__ float g_h[2 * HH * BB];            // ping-pong h state, k-major [k][b]
__device__ float g_hs[SS * HH * BB];          // full h history [t][k][b]  (256 MB)
__device__ float g_hid[SS * MM * BB];         // mlp hidden [s][m][b]      (134 MB)
__device__ unsigned int g_bar;

// ---------------- helpers ----------------
__device__ __forceinline__ unsigned long long ldg64cg(const float* p) {
    unsigned long long v;
    asm("ld.global.cg.b64 %0, [%1];" : "=l"(v) : "l"(p));
    return v;
}
__device__ __forceinline__ void fma2(unsigned long long& acc, unsigned long long w,
                                     unsigned long long h) {
    asm("fma.rn.f32x2 %0, %1, %2, %0;" : "+l"(acc) : "l"(w), "l"(h));
}
__device__ __forceinline__ unsigned long long pk2(float a, float b) {
    unsigned long long v;
    asm("mov.b64 %0, {%1, %2};" : "=l"(v) : "f"(a), "f"(b));
    return v;
}
__device__ __forceinline__ float2 up2(unsigned long long v) {
    float2 r;
    asm("mov.b64 {%0, %1}, %2;" : "=f"(r.x), "=f"(r.y) : "l"(v));
    return r;
}
__device__ __forceinline__ float sigf(float x) {
    return __fdividef(1.f, 1.f + __expf(-x));
}
__device__ __forceinline__ float tanhfast(float x) {
    // 2*sigmoid(2x)-1 ; saturates correctly for |x| large (expf->inf/0)
    return __fdividef(2.f, 1.f + __expf(-2.f * x)) - 1.f;
}

// ---------------- reset: zero h state + barrier counter ----------------
extern "C" __global__ void reset_kernel() {
    int idx = blockIdx.x * blockDim.x + threadIdx.x;
    if (idx < 2 * HH * BB) g_h[idx] = 0.f;
    if (idx == 0) g_bar = 0u;
}

// ---------------- transpose x -> [t][f][b] ----------------
extern "C" __global__ void xT_kernel(const float* __restrict__ x) {
    int idx = blockIdx.x * blockDim.x + threadIdx.x;
    if (idx >= SS * FF * BB) return;
    int b = idx & (BB - 1);
    int rest = idx >> 8;
    int f = rest % FF;
    int t = rest / FF;
    g_xT[idx] = x[(b * SS + t) * FF + f];
}

// ---------------- persistent LSTM kernel ----------------
extern "C" __global__ void __launch_bounds__(NTHR, 1)
lstm_kernel(const float* __restrict__ w_hh, const float* __restrict__ w_ih,
            const float* __restrict__ b_ih, const float* __restrict__ b_hh) {
    extern __shared__ float smem[];
    float2* w2  = (float2*)smem;                          // [NROW][HH] dup'd {w,w}
    float2* wx2 = (float2*)(smem + NROW * HH * 2);        // [NROW][28] dup'd
    float*  bsh = smem + NROW * HH * 2 + NROW * 28 * 2;   // [NROW]

    const int bj  = blockIdx.x;     // hidden-unit tile
    const int tid = threadIdx.x;    // batch-pair

    // Load recurrent weights (SMEM-resident for all 512 steps), duplicated for f32x2
    for (int idx = tid; idx < NROW * HH; idx += NTHR) {
        int r = idx >> 9, k = idx & (HH - 1);
        int g = r & 3, jj = r >> 2;
        float w = w_hh[(g * HH + bj * JT + jj) * HH + k];
        w2[r * HH + k] = make_float2(w, w);
    }
    for (int idx = tid; idx < NROW * FF; idx += NTHR) {
        int r = idx / FF, f = idx % FF;
        int g = r & 3, jj = r >> 2;
        float w = w_ih[(g * HH + bj * JT + jj) * FF + f];
        wx2[r * 28 + f] = make_float2(w, w);
    }
    if (tid < NROW) {
        int g = tid & 3, jj = tid >> 2;
        int row = g * HH + bj * JT + jj;
        bsh[tid] = b_ih[row] + b_hh[row];
    }
    __syncthreads();

    const int p2 = tid * 2;         // batch-pair base index
    float2 c_st[JT];
#pragma unroll
    for (int j = 0; j < JT; j++) c_st[j] = make_float2(0.f, 0.f);

    for (int t = 0; t < SS; t++) {
        unsigned long long acc[NROW];
#pragma unroll
        for (int r = 0; r < NROW; r++) acc[r] = pk2(bsh[r], bsh[r]);

        // ---- input part: z += x_t @ w_ih^T  (K = 26) ----
        const float* xs = g_xT + t * FF * BB;
#pragma unroll
        for (int f = 0; f < FF; f += 2) {
            unsigned long long xa = ldg64cg(xs + f * BB + p2);
            unsigned long long xb = ldg64cg(xs + (f + 1) * BB + p2);
#pragma unroll
            for (int r = 0; r < NROW; r++) {
                ulonglong2 ww = *(const ulonglong2*)(&wx2[r * 28 + f]);
                fma2(acc[r], ww.x, xa);
                fma2(acc[r], ww.y, xb);
            }
        }

        // ---- recurrent part: z += h @ w_hh^T  (K = 512) ----
        const float* hsrc = g_h + (t & 1) * HH * BB;
#pragma unroll 4
        for (int k = 0; k < HH; k += 2) {
            unsigned long long ha = ldg64cg(hsrc + k * BB + p2);
            unsigned long long hb = ldg64cg(hsrc + (k + 1) * BB + p2);
#pragma unroll
            for (int r = 0; r < NROW; r++) {
                ulonglong2 ww = *(const ulonglong2*)(&w2[r * HH + k]);
                fma2(acc[r], ww.x, ha);
                fma2(acc[r], ww.y, hb);
            }
        }

        // ---- gates + state update (c kept in registers) ----
        float* hdst = g_h + ((t + 1) & 1) * HH * BB;
        float* hrec = g_hs + t * HH * BB;
#pragma unroll
        for (int jj = 0; jj < JT; jj++) {
            float2 zi = up2(acc[jj * 4 + 0]);
            float2 zf = up2(acc[jj * 4 + 1]);
            float2 zg = up2(acc[jj * 4 + 2]);
            float2 zo = up2(acc[jj * 4 + 3]);
            float2 c = c_st[jj];
            c.x = sigf(zf.x) * c.x + sigf(zi.x) * tanhfast(zg.x);
            c.y = sigf(zf.y) * c.y + sigf(zi.y) * tanhfast(zg.y);
            float2 h;
            h.x = sigf(zo.x) * tanhfast(c.x);
            h.y = sigf(zo.y) * tanhfast(c.y);
            c_st[jj] = c;
            int j = bj * JT + jj;
            *(float2*)(hdst + j * BB + p2) = h;
            *(float2*)(hrec + j * BB + p2) = h;
        }

        // ---- grid barrier (all 128 blocks resident by construction) ----
        __syncthreads();
        if (tid == 0) {
            __threadfence();
            atomicAdd(&g_bar, 1u);
            unsigned int tgt = (unsigned int)gridDim.x * (unsigned int)(t + 1);
            while (*(volatile unsigned int*)&g_bar < tgt) { }
            __threadfence();
        }
        __syncthreads();
    }
}

// ---------------- MLP layer 1: hidden = relu(hs @ w1^T + b1) ----------------
extern "C" __global__ void __launch_bounds__(NTHR)
mlp1_kernel(const float* __restrict__ w1, const float* __restrict__ b1) {
    extern __shared__ float smem[];
    float2* wsh = (float2*)smem;          // [16][HH] dup'd
    float*  bsh = smem + 16 * HH * 2;     // [16]
    const int mt  = blockIdx.x;           // 0..15 m-tile
    const int s   = blockIdx.y;           // 0..511
    const int tid = threadIdx.x;

    for (int idx = tid; idx < 16 * HH; idx += NTHR) {
        int r = idx >> 9, k = idx & (HH - 1);
        float w = w1[(mt * 16 + r) * HH + k];
        wsh[r * HH + k] = make_float2(w, w);
    }
    if (tid < 16) bsh[tid] = b1[mt * 16 + tid];
    __syncthreads();

    const int p2 = tid * 2;
    unsigned long long acc[16];
#pragma unroll
    for (int r = 0; r < 16; r++) acc[r] = pk2(bsh[r], bsh[r]);

    const float* hs = g_hs + s * HH * BB;
#pragma unroll 4
    for (int k = 0; k < HH; k += 2) {
        unsigned long long ha = ldg64cg(hs + k * BB + p2);
        unsigned long long hb = ldg64cg(hs + (k + 1) * BB + p2);
#pragma unroll
        for (int r = 0; r < 16; r++) {
            ulonglong2 ww = *(const ulonglong2*)(&wsh[r * HH + k]);
            fma2(acc[r], ww.x, ha);
            fma2(acc[r], ww.y, hb);
        }
    }
    float* outp = g_hid + s * MM * BB;
#pragma unroll
    for (int r = 0; r < 16; r++) {
        float2 v = up2(acc[r]);
        v.x = fmaxf(v.x, 0.f);
        v.y = fmaxf(v.y, 0.f);
        *(float2*)(outp + (mt * 16 + r) * BB + p2) = v;
    }
}

// ---------------- MLP layer 2 + log_softmax ----------------
#define BT 32
extern "C" __global__ void __launch_bounds__(128)
mlp2_kernel(const float* __restrict__ w2, const float* __restrict__ b2,
            float* __restrict__ out) {
    __shared__ float hsh[MM][BT + 1];   // padded: bank-conflict-free column reads
    __shared__ float lsh[BT][CC + 1];
    const int s   = blockIdx.x;   // 0..511
    const int bt  = blockIdx.y;   // 0..7
    const int tid = threadIdx.x;

    const float* hid = g_hid + s * MM * BB + bt * BT;
    for (int idx = tid; idx < MM * BT; idx += 128) {
        int m = idx >> 5, b = idx & 31;
        hsh[m][b] = hid[m * BB + b];
    }
    __syncthreads();

    const int b = tid & 31, cg = tid >> 5;   // cg in 0..3
    for (int ci = 0; ci < CC; ci += 4) {
        int c = ci + cg;
        float acc = b2[c];
        const float* w2r = w2 + c * MM;
#pragma unroll 8
        for (int m = 0; m < MM; m++) acc += hsh[m][b] * __ldg(&w2r[m]);
        lsh[b][c] = acc;
    }
    __syncthreads();

    if (tid < BT) {
        float mx = -1e30f;
#pragma unroll
        for (int c = 0; c < CC; c++) mx = fmaxf(mx, lsh[tid][c]);
        float sum = 0.f;
#pragma unroll
        for (int c = 0; c < CC; c++) sum += __expf(lsh[tid][c] - mx);
        float lse = mx + logf(sum);
        float* op = out + ((size_t)(bt * BT + tid) * SS + s) * CC;
#pragma unroll
        for (int c = 0; c < CC; c++) op[c] = lsh[tid][c] - lse;
    }
}

// ---------------- launch ----------------
extern "C" void kernel_launch(void* const* d_in, const int* in_sizes, int n_in,
                              void* d_out, int out_size) {
    const float* x    = (const float*)d_in[0];
    const float* w_ih = (const float*)d_in[1];
    const float* w_hh = (const float*)d_in[2];
    const float* b_ih = (const float*)d_in[3];
    const float* b_hh = (const float*)d_in[4];
    const float* w1   = (const float*)d_in[5];
    const float* b1   = (const float*)d_in[6];
    const float* w2   = (const float*)d_in[7];
    const float* b2   = (const float*)d_in[8];
    float* out = (float*)d_out;

    // >48KB dynamic SMEM opt-in (idempotent, not a stream op)
    cudaFuncSetAttribute(lstm_kernel, cudaFuncAttributeMaxDynamicSharedMemorySize,
                         LSTM_SMEM);
    cudaFuncSetAttribute(mlp1_kernel, cudaFuncAttributeMaxDynamicSharedMemorySize,
                         MLP1_SMEM);

    reset_kernel<<<(2 * HH * BB + 255) / 256, 256>>>();
    xT_kernel<<<(SS * FF * BB + 255) / 256, 256>>>(x);
    lstm_kernel<<<NBLK, NTHR, LSTM_SMEM>>>(w_hh, w_ih, b_ih, b_hh);
    dim3 g1(16, SS);
    mlp1_kernel<<<g1, NTHR, MLP1_SMEM>>>(w1, b1);
    dim3 g2(SS, BB / BT);
    mlp2_kernel<<<g2, 128>>>(w2, b2, out);
}

// round 7
// speedup vs baseline: 1.1124x; 1.1124x over previous
#include <cuda_runtime.h>
#include <math.h>

// Problem dims
#define BB 256
#define SS 512
#define FF 26
#define HH 512
#define MM 256
#define CC 20

// LSTM kernel config
#define NBLK 128        // hidden-unit tiles (4 units each)
#define JT 4            // hidden units per block
#define NROW 16         // 4 gates * JT rows
#define NTHR 256        // 4 k-groups x 64 pair-slot threads
#define KX 544          // 512 h + 26 x + 6 zero pad  (544 = 4*136)
#define KG 136          // k per group
#define KPAIRS 68       // k-pairs per group

// smem: w2 (float2[16*KX]) + sbuf (ulonglong2[4*16*64]) + bias[16]
#define LSTM_SMEM (16*KX*8 + 4*16*64*16 + 16*4)
#define MLP1_SMEM ((16*HH*2 + 16) * 4)

// ---------------- scratch (static __device__, allocation-free) ----------------
__device__ float g_xT[SS * FF * BB];          // x transposed: [t][f][b]
__device__ float g_hx[2 * KX * BB];           // ping-pong state [k|x|pad][b]
__device__ float g_hs[SS * HH * BB];          // full h history [t][k][b]
__device__ float g_hid[SS * MM * BB];         // mlp hidden [s][m][b]
__device__ unsigned int g_bar;

// ---------------- helpers ----------------
__device__ __forceinline__ unsigned long long ldg64cg(const float* p) {
    unsigned long long v;
    asm("ld.global.cg.b64 %0, [%1];" : "=l"(v) : "l"(p));
    return v;
}
__device__ __forceinline__ void fma2(unsigned long long& acc, unsigned long long w,
                                     unsigned long long h) {
    asm("fma.rn.f32x2 %0, %1, %2, %0;" : "+l"(acc) : "l"(w), "l"(h));
}
__device__ __forceinline__ void fadd2(unsigned long long& a, unsigned long long b) {
    asm("add.rn.f32x2 %0, %0, %1;" : "+l"(a) : "l"(b));
}
__device__ __forceinline__ unsigned long long pk2(float a, float b) {
    unsigned long long v;
    asm("mov.b64 %0, {%1, %2};" : "=l"(v) : "f"(a), "f"(b));
    return v;
}
__device__ __forceinline__ float2 up2(unsigned long long v) {
    float2 r;
    asm("mov.b64 {%0, %1}, %2;" : "=f"(r.x), "=f"(r.y) : "l"(v));
    return r;
}
__device__ __forceinline__ float sigf(float x) {
    return __fdividef(1.f, 1.f + __expf(-x));
}
__device__ __forceinline__ float tanhfast(float x) {
    return __fdividef(2.f, 1.f + __expf(-2.f * x)) - 1.f;
}

// ---------------- reset: zero state + barrier counter ----------------
extern "C" __global__ void reset_kernel() {
    int idx = blockIdx.x * blockDim.x + threadIdx.x;
    if (idx < 2 * KX * BB) g_hx[idx] = 0.f;
    if (idx == 0) g_bar = 0u;
}

// ---------------- transpose x -> [t][f][b] ----------------
extern "C" __global__ void xT_kernel(const float* __restrict__ x) {
    int idx = blockIdx.x * blockDim.x + threadIdx.x;
    if (idx >= SS * FF * BB) return;
    int b = idx & (BB - 1);
    int rest = idx >> 8;
    int f = rest % FF;
    int t = rest / FF;
    g_xT[idx] = x[(b * SS + t) * FF + f];
}

// ---------------- seed x_0 into state buffer 0 ----------------
extern "C" __global__ void seedx_kernel(const float* __restrict__ x) {
    int idx = blockIdx.x * blockDim.x + threadIdx.x;
    if (idx >= FF * BB) return;
    int f = idx >> 8, b = idx & 255;
    g_hx[(HH + f) * BB + b] = x[b * SS * FF + f];
}

// ---------------- persistent LSTM kernel ----------------
extern "C" __global__ void __launch_bounds__(NTHR, 1)
lstm_kernel(const float* __restrict__ w_hh, const float* __restrict__ w_ih,
            const float* __restrict__ b_ih, const float* __restrict__ b_hh) {
    extern __shared__ float smem[];
    float2* w2 = (float2*)smem;                                   // [16][KX] dup'd
    ulonglong2* sbuf = (ulonglong2*)(smem + 16 * KX * 2);         // [4][16][64]
    float* bsh = (float*)(sbuf + 4 * 16 * 64);                    // [16]

    const int bj  = blockIdx.x;      // hidden-unit tile (4 units)
    const int tid = threadIdx.x;
    const int g   = tid >> 6;        // k-group 0..3
    const int j   = tid & 63;        // pair-slot: pairs j and j+64
    const int j2  = j * 2;

    // Load weights (SMEM-resident all 512 steps), duplicated for f32x2.
    // Row r = jj*4 + gate; k<512: w_hh, 512..537: w_ih, 538..543: 0.
    for (int idx = tid; idx < NROW * KX; idx += NTHR) {
        int r = idx / KX, k = idx % KX;
        int gate = r & 3, jj = r >> 2;
        int grow = gate * HH + bj * JT + jj;
        float w = 0.f;
        if (k < HH) w = w_hh[grow * HH + k];
        else if (k < HH + FF) w = w_ih[grow * FF + (k - HH)];
        w2[r * KX + k] = make_float2(w, w);
    }
    if (tid < NROW) {
        int gate = tid & 3, jj = tid >> 2;
        int grow = gate * HH + bj * JT + jj;
        bsh[tid] = b_ih[grow] + b_hh[grow];
    }
    __syncthreads();

    const int kbase = g * KG;
    const float2* wrow = w2 + kbase;   // row-relative base for this group

    // c state: this thread owns unit (bj*4+g), pairs j and j+64
    float2 c0 = make_float2(0.f, 0.f), c1 = make_float2(0.f, 0.f);

    for (int t = 0; t < SS; t++) {
        unsigned long long acc[NROW][2];
        if (g == 0) {
#pragma unroll
            for (int r = 0; r < NROW; r++) {
                unsigned long long bv = pk2(bsh[r], bsh[r]);
                acc[r][0] = bv; acc[r][1] = bv;
            }
        } else {
#pragma unroll
            for (int r = 0; r < NROW; r++) { acc[r][0] = 0ull; acc[r][1] = 0ull; }
        }

        // ---- z partial over this group's k range (h + folded-in x) ----
        const float* hsrc = g_hx + (t & 1) * KX * BB + kbase * BB;
#pragma unroll 4
        for (int kp = 0; kp < KPAIRS; kp++) {
            const float* hp = hsrc + kp * 2 * BB;
            unsigned long long ha0 = ldg64cg(hp + j2);
            unsigned long long ha1 = ldg64cg(hp + 128 + j2);
            unsigned long long hb0 = ldg64cg(hp + BB + j2);
            unsigned long long hb1 = ldg64cg(hp + BB + 128 + j2);
#pragma unroll
            for (int r = 0; r < NROW; r++) {
                ulonglong2 ww = *(const ulonglong2*)(wrow + r * KX + kp * 2);
                fma2(acc[r][0], ww.x, ha0);
                fma2(acc[r][1], ww.x, ha1);
                fma2(acc[r][0], ww.y, hb0);
                fma2(acc[r][1], ww.y, hb1);
            }
        }

        // ---- cross-group reduction through smem ----
#pragma unroll
        for (int r = 0; r < NROW; r++) {
            ulonglong2 v; v.x = acc[r][0]; v.y = acc[r][1];
            sbuf[(g * 16 + r) * 64 + j] = v;
        }
        __syncthreads();
        const int r0 = g * 4;   // my unit's 4 gate rows
#pragma unroll
        for (int gg = 0; gg < 4; gg++) {
            if (gg == g) continue;
#pragma unroll
            for (int rr = 0; rr < 4; rr++) {
                ulonglong2 v = sbuf[(gg * 16 + r0 + rr) * 64 + j];
                fadd2(acc[r0 + rr][0], v.x);
                fadd2(acc[r0 + rr][1], v.y);
            }
        }

        // ---- gates + state update for unit (bj*4+g), pairs j and j+64 ----
        float2 zi0 = up2(acc[r0 + 0][0]), zi1 = up2(acc[r0 + 0][1]);
        float2 zf0 = up2(acc[r0 + 1][0]), zf1 = up2(acc[r0 + 1][1]);
        float2 zg0 = up2(acc[r0 + 2][0]), zg1 = up2(acc[r0 + 2][1]);
        float2 zo0 = up2(acc[r0 + 3][0]), zo1 = up2(acc[r0 + 3][1]);

        c0.x = sigf(zf0.x) * c0.x + sigf(zi0.x) * tanhfast(zg0.x);
        c0.y = sigf(zf0.y) * c0.y + sigf(zi0.y) * tanhfast(zg0.y);
        c1.x = sigf(zf1.x) * c1.x + sigf(zi1.x) * tanhfast(zg1.x);
        c1.y = sigf(zf1.y) * c1.y + sigf(zi1.y) * tanhfast(zg1.y);
        float2 h0, h1;
        h0.x = sigf(zo0.x) * tanhfast(c0.x);
        h0.y = sigf(zo0.y) * tanhfast(c0.y);
        h1.x = sigf(zo1.x) * tanhfast(c1.x);
        h1.y = sigf(zo1.y) * tanhfast(c1.y);

        const int unit = bj * JT + g;
        float* hd = g_hx + ((t + 1) & 1) * KX * BB + unit * BB;
        *(float2*)(hd + j2) = h0;
        *(float2*)(hd + 128 + j2) = h1;
        float* hr = g_hs + t * HH * BB + unit * BB;
        *(float2*)(hr + j2) = h0;
        *(float2*)(hr + 128 + j2) = h1;

        // ---- feed x_{t+1} into next state buffer (52 floats per block) ----
        if (t + 1 < SS && tid < 52) {
            int base = bj * 52 + tid;           // 0..6655 = 26*256
            int f = base >> 8, b = base & 255;
            g_hx[((t + 1) & 1) * KX * BB + (HH + f) * BB + b] =
                g_xT[(t + 1) * FF * BB + f * BB + b];
        }

        // ---- grid barrier (128 blocks, all resident) ----
        __syncthreads();
        if (tid == 0) {
            __threadfence();
            atomicAdd(&g_bar, 1u);
            unsigned int tgt = (unsigned int)gridDim.x * (unsigned int)(t + 1);
            while (*(volatile unsigned int*)&g_bar < tgt) { }
            __threadfence();
        }
        __syncthreads();
    }
}

// ---------------- MLP layer 1: hidden = relu(hs @ w1^T + b1) ----------------
extern "C" __global__ void __launch_bounds__(128)
mlp1_kernel(const float* __restrict__ w1, const float* __restrict__ b1) {
    extern __shared__ float smem[];
    float2* wsh = (float2*)smem;          // [16][HH] dup'd
    float*  bsh = smem + 16 * HH * 2;     // [16]
    const int mt  = blockIdx.x;           // 0..15 m-tile
    const int s   = blockIdx.y;           // 0..511
    const int tid = threadIdx.x;

    for (int idx = tid; idx < 16 * HH; idx += 128) {
        int r = idx >> 9, k = idx & (HH - 1);
        float w = w1[(mt * 16 + r) * HH + k];
        wsh[r * HH + k] = make_float2(w, w);
    }
    if (tid < 16) bsh[tid] = b1[mt * 16 + tid];
    __syncthreads();

    const int p2 = tid * 2;
    unsigned long long acc[16];
#pragma unroll
    for (int r = 0; r < 16; r++) acc[r] = pk2(bsh[r], bsh[r]);

    const float* hs = g_hs + s * HH * BB;
#pragma unroll 4
    for (int k = 0; k < HH; k += 2) {
        unsigned long long ha = ldg64cg(hs + k * BB + p2);
        unsigned long long hb = ldg64cg(hs + (k + 1) * BB + p2);
#pragma unroll
        for (int r = 0; r < 16; r++) {
            ulonglong2 ww = *(const ulonglong2*)(&wsh[r * HH + k]);
            fma2(acc[r], ww.x, ha);
            fma2(acc[r], ww.y, hb);
        }
    }
    float* outp = g_hid + s * MM * BB;
#pragma unroll
    for (int r = 0; r < 16; r++) {
        float2 v = up2(acc[r]);
        v.x = fmaxf(v.x, 0.f);
        v.y = fmaxf(v.y, 0.f);
        *(float2*)(outp + (mt * 16 + r) * BB + p2) = v;
    }
}

// ---------------- MLP layer 2 + log_softmax ----------------
#define BT 32
extern "C" __global__ void __launch_bounds__(128)
mlp2_kernel(const float* __restrict__ w2, const float* __restrict__ b2,
            float* __restrict__ out) {
    __shared__ float hsh[MM][BT + 1];
    __shared__ float lsh[BT][CC + 1];
    const int s   = blockIdx.x;
    const int bt  = blockIdx.y;
    const int tid = threadIdx.x;

    const float* hid = g_hid + s * MM * BB + bt * BT;
    for (int idx = tid; idx < MM * BT; idx += 128) {
        int m = idx >> 5, b = idx & 31;
        hsh[m][b] = hid[m * BB + b];
    }
    __syncthreads();

    const int b = tid & 31, cg = tid >> 5;
    for (int ci = 0; ci < CC; ci += 4) {
        int c = ci + cg;
        float acc = b2[c];
        const float* w2r = w2 + c * MM;
#pragma unroll 8
        for (int m = 0; m < MM; m++) acc += hsh[m][b] * __ldg(&w2r[m]);
        lsh[b][c] = acc;
    }
    __syncthreads();

    if (tid < BT) {
        float mx = -1e30f;
#pragma unroll
        for (int c = 0; c < CC; c++) mx = fmaxf(mx, lsh[tid][c]);
        float sum = 0.f;
#pragma unroll
        for (int c = 0; c < CC; c++) sum += __expf(lsh[tid][c] - mx);
        float lse = mx + logf(sum);
        float* op = out + ((size_t)(bt * BT + tid) * SS + s) * CC;
#pragma unroll
        for (int c = 0; c < CC; c++) op[c] = lsh[tid][c] - lse;
    }
}

// ---------------- launch ----------------
extern "C" void kernel_launch(void* const* d_in, const int* in_sizes, int n_in,
                              void* d_out, int out_size) {
    const float* x    = (const float*)d_in[0];
    const float* w_ih = (const float*)d_in[1];
    const float* w_hh = (const float*)d_in[2];
    const float* b_ih = (const float*)d_in[3];
    const float* b_hh = (const float*)d_in[4];
    const float* w1   = (const float*)d_in[5];
    const float* b1   = (const float*)d_in[6];
    const float* w2   = (const float*)d_in[7];
    const float* b2   = (const float*)d_in[8];
    float* out = (float*)d_out;

    cudaFuncSetAttribute(lstm_kernel, cudaFuncAttributeMaxDynamicSharedMemorySize,
                         LSTM_SMEM);
    cudaFuncSetAttribute(mlp1_kernel, cudaFuncAttributeMaxDynamicSharedMemorySize,
                         MLP1_SMEM);

    reset_kernel<<<(2 * KX * BB + 255) / 256, 256>>>();
    xT_kernel<<<(SS * FF * BB + 255) / 256, 256>>>(x);
    seedx_kernel<<<(FF * BB + 255) / 256, 256>>>(x);
    lstm_kernel<<<NBLK, NTHR, LSTM_SMEM>>>(w_hh, w_ih, b_ih, b_hh);
    dim3 g1(16, SS);
    mlp1_kernel<<<g1, 128, MLP1_SMEM>>>(w1, b1);
    dim3 g2(SS, BB / BT);
    mlp2_kernel<<<g2, 128>>>(w2, b2, out);
}